// round 16
// baseline (speedup 1.0000x reference)
#include <cuda_runtime.h>
#include <cuda_bf16.h>
#include <math.h>
#include <stdint.h>

// Problem dims (fixed by the reference)
#define B_SZ 1024
#define D_SZ 2048
#define N_SZ 30000

// ---------------------------------------------------------------------------
// Scratch (static __device__ arrays — allowed; no dynamic allocation)
// g_Atf / g_Ftf hold tf32-pre-rounded fp32 operands (rounded once, so the
// GEMM inner loop needs no cvt instructions; numerics identical to rounding
// in-loop).
// ---------------------------------------------------------------------------
__device__ int g_winner[N_SZ];
__device__ float g_Atf[(size_t)B_SZ * D_SZ];
__device__ float g_Ftf[(size_t)N_SZ * D_SZ];

// ---------------------------------------------------------------------------
// PTX helpers — base-sm_103-legal only (sm_80-era): mma.sync tf32, ldmatrix,
// cp.async. (tcgen05 rejected by this toolchain's base-sm_103 ptxas target.)
// ---------------------------------------------------------------------------
__device__ __forceinline__ uint32_t smem_u32(const void* p) {
    uint32_t a;
    asm("{ .reg .u64 t; cvta.to.shared.u64 t, %1; cvt.u32.u64 %0, t; }"
        : "=r"(a) : "l"(p));
    return a;
}

#define LDSM_X4(r, addr) \
    asm volatile("ldmatrix.sync.aligned.m8n8.x4.shared.b16 {%0,%1,%2,%3}, [%4];" \
        : "=r"((r)[0]), "=r"((r)[1]), "=r"((r)[2]), "=r"((r)[3]) : "r"(addr))

#define MMA_TF32(d, a, b) \
    asm volatile("mma.sync.aligned.m16n8k8.row.col.f32.tf32.tf32.f32 " \
        "{%0,%1,%2,%3}, {%4,%5,%6,%7}, {%8,%9}, {%0,%1,%2,%3};" \
        : "+f"((d)[0]), "+f"((d)[1]), "+f"((d)[2]), "+f"((d)[3]) \
        : "r"((a)[0]), "r"((a)[1]), "r"((a)[2]), "r"((a)[3]), \
          "r"((b)[0]), "r"((b)[1]))

#define CP_ASYNC_16(daddr, gptr, nbytes) \
    asm volatile("cp.async.cg.shared.global [%0], [%1], 16, %2;" \
        :: "r"(daddr), "l"(gptr), "r"(nbytes) : "memory")
#define CP_ASYNC_COMMIT() asm volatile("cp.async.commit_group;" ::: "memory")
#define CP_ASYNC_WAIT_2() asm volatile("cp.async.wait_group 2;" ::: "memory")

// round-to-nearest fp32 -> tf32 (value-preserving fp32 encoding)
__device__ __forceinline__ float tf32_rna(float x) {
    uint32_t u = __float_as_uint(x);
    asm("cvt.rna.tf32.f32 %0, %0;" : "+r"(u));
    return __uint_as_float(u);
}

// ---------------------------------------------------------------------------
// Kernel: round A (inputs) to tf32 scratch. 8 MB, trivial.
// ---------------------------------------------------------------------------
__global__ void convert_a_kernel(const float* __restrict__ A) {
    size_t i = (size_t)blockIdx.x * blockDim.x + threadIdx.x;   // float4 id
    float4 v = reinterpret_cast<const float4*>(A)[i];
    v.x = tf32_rna(v.x); v.y = tf32_rna(v.y);
    v.z = tf32_rna(v.z); v.w = tf32_rna(v.w);
    reinterpret_cast<float4*>(g_Atf)[i] = v;
}

// ---------------------------------------------------------------------------
// Fused kernel: one block per feature row. Streams the row ONCE from DRAM:
//  (a) writes tf32-rounded copy to g_Ftf (GEMM operand)
//  (b) produces new_features row (winner overwrite + renorm) to out_feats
// ---------------------------------------------------------------------------
__global__ void convert_update_kernel(const float* __restrict__ inputs,
                                      const float* __restrict__ feats,
                                      float* __restrict__ out_feats) {
    int y = blockIdx.x;
    int t = threadIdx.x;            // 0..255, 8 floats each (2 x float4)
    int w = g_winner[y];

    const float* frow = feats + (size_t)y * D_SZ;
    float4 f0 = *reinterpret_cast<const float4*>(frow + t * 4);
    float4 f1 = *reinterpret_cast<const float4*>(frow + 1024 + t * 4);

    // (a) tf32-rounded copy for the GEMM
    {
        float4 r0, r1;
        r0.x = tf32_rna(f0.x); r0.y = tf32_rna(f0.y);
        r0.z = tf32_rna(f0.z); r0.w = tf32_rna(f0.w);
        r1.x = tf32_rna(f1.x); r1.y = tf32_rna(f1.y);
        r1.z = tf32_rna(f1.z); r1.w = tf32_rna(f1.w);
        float* drow = g_Ftf + (size_t)y * D_SZ;
        *reinterpret_cast<float4*>(drow + t * 4)        = r0;
        *reinterpret_cast<float4*>(drow + 1024 + t * 4) = r1;
    }

    // (b) new_features row
    float* dst = out_feats + (size_t)y * D_SZ;
    float4 v0 = f0, v1 = f1;
    if (w >= 0) {  // overwritten by inputs[w]
        const float* src = inputs + (size_t)w * D_SZ;
        v0 = *reinterpret_cast<const float4*>(src + t * 4);
        v1 = *reinterpret_cast<const float4*>(src + 1024 + t * 4);
    }
    if (w == -2) {  // untouched: plain copy
        *reinterpret_cast<float4*>(dst + t * 4)        = v0;
        *reinterpret_cast<float4*>(dst + 1024 + t * 4) = v1;
        return;
    }

    float ss = v0.x * v0.x + v0.y * v0.y + v0.z * v0.z + v0.w * v0.w
             + v1.x * v1.x + v1.y * v1.y + v1.z * v1.z + v1.w * v1.w;
    #pragma unroll
    for (int o = 16; o > 0; o >>= 1)
        ss += __shfl_xor_sync(0xffffffffu, ss, o);

    __shared__ float sred[8];
    __shared__ float stot;
    if ((t & 31) == 0) sred[t >> 5] = ss;
    __syncthreads();
    if (t < 8) {
        float v = sred[t];
        v += __shfl_xor_sync(0x000000ffu, v, 4);
        v += __shfl_xor_sync(0x000000ffu, v, 2);
        v += __shfl_xor_sync(0x000000ffu, v, 1);
        if (t == 0) stot = v;
    }
    __syncthreads();

    float inv = 1.0f / fmaxf(sqrtf(stot), 1e-12f);
    v0.x *= inv; v0.y *= inv; v0.z *= inv; v0.w *= inv;
    v1.x *= inv; v1.y *= inv; v1.z *= inv; v1.w *= inv;
    *reinterpret_cast<float4*>(dst + t * 4)        = v0;
    *reinterpret_cast<float4*>(dst + 1024 + t * 4) = v1;
}

// ---------------------------------------------------------------------------
// TF32 HMMA GEMM:  C[m][n] = sum_k A[m][k] * F[n][k], pre-rounded operands.
// CTA tile 256x128, BK=32, 256 threads = 8 warps (4M x 2N), warp tile 64x64,
// m16n8k8 fragments via the ldmatrix-as-8x4-fp32 trick. No in-loop cvt.
// 3-stage cp.async pipeline, always-commit + wait_group 2.
// Row pad 144B: ldmatrix row word-addrs = 4r mod 32 -> conflict-free.
// ---------------------------------------------------------------------------
#define BK 32
#define ROW_B 144
#define ARR_A (256 * ROW_B)              // 36864
#define ARR_F (128 * ROW_B)              // 18432
#define STAGE_BYTES (ARR_A + ARR_F)      // 55296
#define N_STAGE 3
#define SMEM_DYN (N_STAGE * STAGE_BYTES) // 165888

__device__ __forceinline__ void issue_tile_loads(
    uint32_t stb, int k0, int tid, int n0,
    const float* __restrict__ A, const float* __restrict__ F)
{
    // 3072 16B chunks: rows 0..255 = A, 256..383 = F; 8 segs per row.
    // i<8 -> A (uniform per i), i>=8 -> F.
    #pragma unroll
    for (int i = 0; i < 12; i++) {
        int idx = i * 256 + tid;
        int row = idx >> 3;
        int seg = idx & 7;
        if (i < 8) {
            uint32_t daddr = stb + row * ROW_B + seg * 16;
            const void* gp = A + (size_t)row * D_SZ + k0 + seg * 4;
            CP_ASYNC_16(daddr, gp, 16);
        } else {
            int frow = row - 256;
            uint32_t daddr = stb + ARR_A + frow * ROW_B + seg * 16;
            const void* gp = F + (size_t)frow * D_SZ + k0 + seg * 4;
            int nbytes = (n0 + frow < N_SZ) ? 16 : 0;   // 0 => zero-fill
            CP_ASYNC_16(daddr, gp, nbytes);
        }
    }
    CP_ASYNC_COMMIT();
}

__global__ __launch_bounds__(256, 1)
void mma_gemm_kernel(float* __restrict__ C) {
    extern __shared__ char smem[];
    const uint32_t sb = smem_u32(smem);
    const int tid  = threadIdx.x;
    const int lane = tid & 31;
    const int wid  = tid >> 5;
    const int warp_m = wid & 3;     // 4 warps over M (64 rows each)
    const int warp_n = wid >> 2;    // 2 warps over N (64 cols each)

    const int m0 = blockIdx.x * 256;
    const int n0 = blockIdx.y * 128;

    const float* A = g_Atf + (size_t)m0 * D_SZ;
    const float* F = g_Ftf + (size_t)n0 * D_SZ;

    float acc[4][8][4];
    #pragma unroll
    for (int mi = 0; mi < 4; mi++)
        #pragma unroll
        for (int nj = 0; nj < 8; nj++)
            #pragma unroll
            for (int r = 0; r < 4; r++)
                acc[mi][nj][r] = 0.0f;

    // ldmatrix lane addressing (mat = lane>>3, r = lane&7), byte offsets.
    // A x4 frag (m16 x k8 as 4 8x4-fp32 mats) -> regs a0..a3 of m16n8k8.
    const int mat = lane >> 3, mr = lane & 7;
    uint32_t a_off[4];
    #pragma unroll
    for (int mi = 0; mi < 4; mi++)
        a_off[mi] = (uint32_t)((warp_m * 64 + mi * 16 + (mat & 1) * 8 + mr) * ROW_B
                               + (mat >> 1) * 16);
    // B x4 covering 16 n rows (2 n-frags): {r0,r1}=frag 2j, {r2,r3}=frag 2j+1.
    uint32_t b_off[4];
    #pragma unroll
    for (int j = 0; j < 4; j++)
        b_off[j] = (uint32_t)((warp_n * 64 + j * 16 + (mat >> 1) * 8 + mr) * ROW_B
                              + (mat & 1) * 16);

    const int NK = D_SZ / BK;   // 64

    issue_tile_loads(sb + 0 * STAGE_BYTES, 0 * BK, tid, n0, A, F);
    issue_tile_loads(sb + 1 * STAGE_BYTES, 1 * BK, tid, n0, A, F);

    for (int c = 0; c < NK; c++) {
        // always commit (possibly-empty group) so wait_group 2 pins stage c
        if (c + 2 < NK)
            issue_tile_loads(sb + ((c + 2) % N_STAGE) * STAGE_BYTES,
                             (c + 2) * BK, tid, n0, A, F);
        else
            CP_ASYNC_COMMIT();
        CP_ASYNC_WAIT_2();
        __syncthreads();

        const uint32_t stb = sb + (c % N_STAGE) * STAGE_BYTES;
        #pragma unroll
        for (int ks = 0; ks < 4; ks++) {          // 4 x k8 per BK=32
            uint32_t a[4][4], b[8][2];
            #pragma unroll
            for (int mi = 0; mi < 4; mi++)
                LDSM_X4(a[mi], stb + a_off[mi] + ks * 32);
            #pragma unroll
            for (int j = 0; j < 4; j++) {
                uint32_t t[4];
                LDSM_X4(t, stb + ARR_A + b_off[j] + ks * 32);
                b[2*j][0] = t[0]; b[2*j][1] = t[1];
                b[2*j+1][0] = t[2]; b[2*j+1][1] = t[3];
            }
            #pragma unroll
            for (int mi = 0; mi < 4; mi++)
                #pragma unroll
                for (int nj = 0; nj < 8; nj++)
                    MMA_TF32(acc[mi][nj], a[mi], b[nj]);
        }
        __syncthreads();   // all warps done with stage c before it is refilled
    }

    // Epilogue: m16n8 accum: row = lane>>2 (+8 for c2,c3), col = 2*(lane&3).
    const int r0 = m0 + warp_m * 64 + (lane >> 2);
    const int c0 = n0 + warp_n * 64 + (lane & 3) * 2;
    #pragma unroll
    for (int mi = 0; mi < 4; mi++) {
        #pragma unroll
        for (int nj = 0; nj < 8; nj++) {
            int col = c0 + nj * 8;
            if (col < N_SZ) {   // col even, N even -> pair fully in-bounds
                float2 v01 = make_float2(acc[mi][nj][0], acc[mi][nj][1]);
                float2 v23 = make_float2(acc[mi][nj][2], acc[mi][nj][3]);
                *reinterpret_cast<float2*>(
                    C + (size_t)(r0 + mi * 16) * N_SZ + col) = v01;
                *reinterpret_cast<float2*>(
                    C + (size_t)(r0 + mi * 16 + 8) * N_SZ + col) = v23;
            }
        }
    }
}

// ---------------------------------------------------------------------------
// Winner marking (tiny)
// ---------------------------------------------------------------------------
__global__ void init_winner_kernel() {
    int i = blockIdx.x * blockDim.x + threadIdx.x;
    if (i < N_SZ) g_winner[i] = -2;
}

__global__ void mark_kernel(const int* __restrict__ indexes,
                            const int* __restrict__ update_flag) {
    int i = blockIdx.x * blockDim.x + threadIdx.x;
    if (i < B_SZ) {
        int y = indexes[i];
        int v = (update_flag[i] > 0) ? i : -1;
        if (y >= 0 && y < N_SZ) atomicMax(&g_winner[y], v);
    }
}

// ---------------------------------------------------------------------------
// Launch. Inputs: inputs f32[B,D], features f32[N,D], IoU f32[B] (unused),
// indexes int32[B], update_flag int32[B].
// Output: concat( outputs f32[B,N], new_features f32[N,D] ).
// ---------------------------------------------------------------------------
extern "C" void kernel_launch(void* const* d_in, const int* in_sizes, int n_in,
                              void* d_out, int out_size) {
    const float* inputs      = (const float*)d_in[0];
    const float* features    = (const float*)d_in[1];
    const int*   indexes     = (const int*)d_in[3];
    const int*   update_flag = (const int*)d_in[4];

    float* out       = (float*)d_out;                 // [B, N]
    float* out_feats = out + (size_t)B_SZ * N_SZ;     // [N, D]

    cudaFuncSetAttribute(mma_gemm_kernel,
                         cudaFuncAttributeMaxDynamicSharedMemorySize, SMEM_DYN);

    // 1) winner marking (needed by fused convert+update)
    init_winner_kernel<<<(N_SZ + 255) / 256, 256>>>();
    mark_kernel<<<(B_SZ + 255) / 256, 256>>>(indexes, update_flag);

    // 2) tf32 pre-round A; fused F pre-round + memory-bank update
    convert_a_kernel<<<(B_SZ * D_SZ / 4) / 256, 256>>>(inputs);
    convert_update_kernel<<<N_SZ, 256>>>(inputs, features, out_feats);

    // 3) TF32 tensor-core GEMM — dominant
    {
        dim3 grid(B_SZ / 256, (N_SZ + 127) / 128);   // (4, 235), m fastest
        mma_gemm_kernel<<<grid, 256, SMEM_DYN>>>(out);
    }
}

// round 17
// speedup vs baseline: 1.4365x; 1.4365x over previous
#include <cuda_runtime.h>
#include <cuda_fp16.h>
#include <math.h>
#include <stdint.h>

// Problem dims (fixed by the reference)
#define B_SZ 1024
#define D_SZ 2048
#define N_SZ 30000

// ---------------------------------------------------------------------------
// Scratch (static __device__ arrays — allowed; no dynamic allocation)
// ---------------------------------------------------------------------------
__device__ int g_winner[N_SZ];
__device__ __half g_Ahf[(size_t)B_SZ * D_SZ];
__device__ __half g_Fhf[(size_t)N_SZ * D_SZ];

// ---------------------------------------------------------------------------
// PTX helpers — base-sm_103-legal only (sm_80-era): mma.sync fp16, ldmatrix,
// cp.async. (tcgen05 rejected by this toolchain's base-sm_103 ptxas target.)
// ---------------------------------------------------------------------------
__device__ __forceinline__ uint32_t smem_u32(const void* p) {
    uint32_t a;
    asm("{ .reg .u64 t; cvta.to.shared.u64 t, %1; cvt.u32.u64 %0, t; }"
        : "=r"(a) : "l"(p));
    return a;
}

#define LDSM_X4(r, addr) \
    asm volatile("ldmatrix.sync.aligned.m8n8.x4.shared.b16 {%0,%1,%2,%3}, [%4];" \
        : "=r"((r)[0]), "=r"((r)[1]), "=r"((r)[2]), "=r"((r)[3]) : "r"(addr))

#define MMA_F16(d, a, b) \
    asm volatile("mma.sync.aligned.m16n8k16.row.col.f32.f16.f16.f32 " \
        "{%0,%1,%2,%3}, {%4,%5,%6,%7}, {%8,%9}, {%0,%1,%2,%3};" \
        : "+f"((d)[0]), "+f"((d)[1]), "+f"((d)[2]), "+f"((d)[3]) \
        : "r"((a)[0]), "r"((a)[1]), "r"((a)[2]), "r"((a)[3]), \
          "r"((b)[0]), "r"((b)[1]))

#define CP_ASYNC_16(daddr, gptr, nbytes) \
    asm volatile("cp.async.cg.shared.global [%0], [%1], 16, %2;" \
        :: "r"(daddr), "l"(gptr), "r"(nbytes) : "memory")
#define CP_ASYNC_COMMIT() asm volatile("cp.async.commit_group;" ::: "memory")
#define CP_ASYNC_WAIT_2() asm volatile("cp.async.wait_group 2;" ::: "memory")

// ---------------------------------------------------------------------------
// Kernel: A (inputs) -> fp16 scratch. 8 MB read, 4 MB write. Trivial.
// ---------------------------------------------------------------------------
__global__ void convert_a_kernel(const float* __restrict__ A) {
    size_t i = (size_t)blockIdx.x * blockDim.x + threadIdx.x;   // float4 id
    float4 v = reinterpret_cast<const float4*>(A)[i];
    __half2 h01 = __floats2half2_rn(v.x, v.y);
    __half2 h23 = __floats2half2_rn(v.z, v.w);
    uint2 pack;
    pack.x = *reinterpret_cast<uint32_t*>(&h01);
    pack.y = *reinterpret_cast<uint32_t*>(&h23);
    reinterpret_cast<uint2*>(g_Ahf)[i] = pack;
}

// ---------------------------------------------------------------------------
// Fused kernel: one block per feature row. Streams the row ONCE from DRAM:
//  (a) writes fp16 copy to g_Fhf (GEMM operand)
//  (b) produces new_features row (winner overwrite + renorm) to out_feats
// ---------------------------------------------------------------------------
__global__ void convert_update_kernel(const float* __restrict__ inputs,
                                      const float* __restrict__ feats,
                                      float* __restrict__ out_feats) {
    int y = blockIdx.x;
    int t = threadIdx.x;            // 0..255, 8 floats each (2 x float4)
    int w = g_winner[y];

    const float* frow = feats + (size_t)y * D_SZ;
    float4 f0 = *reinterpret_cast<const float4*>(frow + t * 4);
    float4 f1 = *reinterpret_cast<const float4*>(frow + 1024 + t * 4);

    // (a) fp16 copy for the GEMM
    {
        __half* drow = g_Fhf + (size_t)y * D_SZ;
        __half2 a = __floats2half2_rn(f0.x, f0.y);
        __half2 b = __floats2half2_rn(f0.z, f0.w);
        __half2 c = __floats2half2_rn(f1.x, f1.y);
        __half2 d = __floats2half2_rn(f1.z, f1.w);
        uint2 p0, p1;
        p0.x = *reinterpret_cast<uint32_t*>(&a);
        p0.y = *reinterpret_cast<uint32_t*>(&b);
        p1.x = *reinterpret_cast<uint32_t*>(&c);
        p1.y = *reinterpret_cast<uint32_t*>(&d);
        *reinterpret_cast<uint2*>(drow + t * 4)        = p0;
        *reinterpret_cast<uint2*>(drow + 1024 + t * 4) = p1;
    }

    // (b) new_features row
    float* dst = out_feats + (size_t)y * D_SZ;
    float4 v0 = f0, v1 = f1;
    if (w >= 0) {  // overwritten by inputs[w]
        const float* src = inputs + (size_t)w * D_SZ;
        v0 = *reinterpret_cast<const float4*>(src + t * 4);
        v1 = *reinterpret_cast<const float4*>(src + 1024 + t * 4);
    }
    if (w == -2) {  // untouched: plain copy
        *reinterpret_cast<float4*>(dst + t * 4)        = v0;
        *reinterpret_cast<float4*>(dst + 1024 + t * 4) = v1;
        return;
    }

    float ss = v0.x * v0.x + v0.y * v0.y + v0.z * v0.z + v0.w * v0.w
             + v1.x * v1.x + v1.y * v1.y + v1.z * v1.z + v1.w * v1.w;
    #pragma unroll
    for (int o = 16; o > 0; o >>= 1)
        ss += __shfl_xor_sync(0xffffffffu, ss, o);

    __shared__ float sred[8];
    __shared__ float stot;
    if ((t & 31) == 0) sred[t >> 5] = ss;
    __syncthreads();
    if (t < 8) {
        float v = sred[t];
        v += __shfl_xor_sync(0x000000ffu, v, 4);
        v += __shfl_xor_sync(0x000000ffu, v, 2);
        v += __shfl_xor_sync(0x000000ffu, v, 1);
        if (t == 0) stot = v;
    }
    __syncthreads();

    float inv = 1.0f / fmaxf(sqrtf(stot), 1e-12f);
    v0.x *= inv; v0.y *= inv; v0.z *= inv; v0.w *= inv;
    v1.x *= inv; v1.y *= inv; v1.z *= inv; v1.w *= inv;
    *reinterpret_cast<float4*>(dst + t * 4)        = v0;
    *reinterpret_cast<float4*>(dst + 1024 + t * 4) = v1;
}

// ---------------------------------------------------------------------------
// FP16 HMMA GEMM:  C[m][n] = sum_k A[m][k] * F[n][k], single pass.
// (fp16 mantissa == tf32 mantissa (10 bits) -> same rounding error as the
//  passing tf32 kernel; k16 per instruction -> HALF the MMA issue count.)
// Tile 128x128, BK=32, 256 threads = 8 warps (2M x 4N), warp tile 64x32,
// m16n8k16 fragments, K-contiguous smem, non-trans ldmatrix for A and B
// (proven R14 recipes). 3-stage cp.async pipeline, always-commit + wait 2.
// Row = 64B data + 16B pad (ROW_B=80) -> conflict-free ldmatrix.
// ---------------------------------------------------------------------------
#define BK 32
#define ROW_B 80
#define ARR_BYTES (128 * ROW_B)          // 10240
#define STAGE_BYTES (2 * ARR_BYTES)      // 20480
#define N_STAGE 3
#define SMEM_DYN (N_STAGE * STAGE_BYTES) // 61440

__device__ __forceinline__ void issue_tile_loads(
    uint32_t stb, int k0, int tid, int n0,
    const __half* __restrict__ A, const __half* __restrict__ F)
{
    // 1024 16B chunks: arr (2) x row (128) x seg (4); thread does 4.
    #pragma unroll
    for (int i = 0; i < 4; i++) {
        const int arr = i >> 1;                    // 0 = A, 1 = F
        const __half* base = arr ? F : A;
        int rem = (i & 1) * 256 + tid;             // 0..511
        int row = rem >> 2;                        // 0..127
        int seg = rem & 3;                         // 0..3 (16B = 8 fp16)
        uint32_t daddr = stb + arr * ARR_BYTES + row * ROW_B + seg * 16;
        const void* gp = base + (size_t)row * D_SZ + k0 + seg * 8;
        int nbytes = (arr == 0 || (n0 + row) < N_SZ) ? 16 : 0;  // 0 => zero-fill
        CP_ASYNC_16(daddr, gp, nbytes);
    }
    CP_ASYNC_COMMIT();
}

__global__ __launch_bounds__(256, 1)
void mma_gemm_kernel(float* __restrict__ C) {
    extern __shared__ char smem[];
    const uint32_t sb = smem_u32(smem);
    const int tid  = threadIdx.x;
    const int lane = tid & 31;
    const int wid  = tid >> 5;
    const int warp_m = wid & 1;     // 2 warps over M
    const int warp_n = wid >> 1;    // 4 warps over N

    const int m0 = blockIdx.x * 128;
    const int n0 = blockIdx.y * 128;

    const __half* A = g_Ahf + (size_t)m0 * D_SZ;
    const __half* F = g_Fhf + (size_t)n0 * D_SZ;

    float acc[4][4][4];
    #pragma unroll
    for (int mi = 0; mi < 4; mi++)
        #pragma unroll
        for (int nj = 0; nj < 4; nj++)
            #pragma unroll
            for (int r = 0; r < 4; r++)
                acc[mi][nj][r] = 0.0f;

    // ldmatrix per-lane byte offsets (proven R14 recipes, K-contig b16):
    // A (16x16 frag): row = frag_m + (lane&15), col-half = lane>>4
    uint32_t a_off[4];
    #pragma unroll
    for (int i = 0; i < 4; i++)
        a_off[i] = (uint32_t)((warp_m * 64 + i * 16 + (lane & 15)) * ROW_B
                              + (lane >> 4) * 16);
    // B non-trans x4 covering 16 n-rows x k16: mat = lane>>3
    uint32_t b_off[2];
    {
        int mat = lane >> 3, r = lane & 7;
        #pragma unroll
        for (int j = 0; j < 2; j++)
            b_off[j] = (uint32_t)((warp_n * 32 + j * 16 + ((mat >> 1) << 3) + r) * ROW_B
                                  + ((mat & 1) << 4));
    }

    const int NK = D_SZ / BK;   // 64

    issue_tile_loads(sb + 0 * STAGE_BYTES, 0 * BK, tid, n0, A, F);
    issue_tile_loads(sb + 1 * STAGE_BYTES, 1 * BK, tid, n0, A, F);

    for (int c = 0; c < NK; c++) {
        // always commit (possibly-empty group) so wait_group 2 pins stage c
        if (c + 2 < NK)
            issue_tile_loads(sb + ((c + 2) % N_STAGE) * STAGE_BYTES,
                             (c + 2) * BK, tid, n0, A, F);
        else
            CP_ASYNC_COMMIT();
        CP_ASYNC_WAIT_2();
        __syncthreads();

        const uint32_t stb = sb + (c % N_STAGE) * STAGE_BYTES;
        #pragma unroll
        for (int ks = 0; ks < 2; ks++) {          // 2 x k16 per BK=32
            uint32_t a[4][4], b[4][2];
            #pragma unroll
            for (int i = 0; i < 4; i++)
                LDSM_X4(a[i], stb + a_off[i] + ks * 32);
            #pragma unroll
            for (int j = 0; j < 2; j++) {
                uint32_t t[4];
                LDSM_X4(t, stb + ARR_BYTES + b_off[j] + ks * 32);
                b[2*j][0] = t[0]; b[2*j][1] = t[1];
                b[2*j+1][0] = t[2]; b[2*j+1][1] = t[3];
            }
            #pragma unroll
            for (int mi = 0; mi < 4; mi++)
                #pragma unroll
                for (int nj = 0; nj < 4; nj++)
                    MMA_F16(acc[mi][nj], a[mi], b[nj]);
        }
        __syncthreads();   // all warps done with stage c before it is refilled
    }

    // Epilogue: m16n8 accum: row = lane>>2 (+8 for c2,c3), col = 2*(lane&3).
    const int r0 = m0 + warp_m * 64 + (lane >> 2);
    const int c0 = n0 + warp_n * 32 + (lane & 3) * 2;
    #pragma unroll
    for (int mi = 0; mi < 4; mi++) {
        #pragma unroll
        for (int nj = 0; nj < 4; nj++) {
            int col = c0 + nj * 8;
            if (col < N_SZ) {   // col even, N even -> pair fully in-bounds
                float2 v01 = make_float2(acc[mi][nj][0], acc[mi][nj][1]);
                float2 v23 = make_float2(acc[mi][nj][2], acc[mi][nj][3]);
                *reinterpret_cast<float2*>(
                    C + (size_t)(r0 + mi * 16) * N_SZ + col) = v01;
                *reinterpret_cast<float2*>(
                    C + (size_t)(r0 + mi * 16 + 8) * N_SZ + col) = v23;
            }
        }
    }
}

// ---------------------------------------------------------------------------
// Winner marking (tiny)
// ---------------------------------------------------------------------------
__global__ void init_winner_kernel() {
    int i = blockIdx.x * blockDim.x + threadIdx.x;
    if (i < N_SZ) g_winner[i] = -2;
}

__global__ void mark_kernel(const int* __restrict__ indexes,
                            const int* __restrict__ update_flag) {
    int i = blockIdx.x * blockDim.x + threadIdx.x;
    if (i < B_SZ) {
        int y = indexes[i];
        int v = (update_flag[i] > 0) ? i : -1;
        if (y >= 0 && y < N_SZ) atomicMax(&g_winner[y], v);
    }
}

// ---------------------------------------------------------------------------
// Launch. Inputs: inputs f32[B,D], features f32[N,D], IoU f32[B] (unused),
// indexes int32[B], update_flag int32[B].
// Output: concat( outputs f32[B,N], new_features f32[N,D] ).
// ---------------------------------------------------------------------------
extern "C" void kernel_launch(void* const* d_in, const int* in_sizes, int n_in,
                              void* d_out, int out_size) {
    const float* inputs      = (const float*)d_in[0];
    const float* features    = (const float*)d_in[1];
    const int*   indexes     = (const int*)d_in[3];
    const int*   update_flag = (const int*)d_in[4];

    float* out       = (float*)d_out;                 // [B, N]
    float* out_feats = out + (size_t)B_SZ * N_SZ;     // [N, D]

    cudaFuncSetAttribute(mma_gemm_kernel,
                         cudaFuncAttributeMaxDynamicSharedMemorySize, SMEM_DYN);

    // 1) winner marking (needed by fused convert+update)
    init_winner_kernel<<<(N_SZ + 255) / 256, 256>>>();
    mark_kernel<<<(B_SZ + 255) / 256, 256>>>(indexes, update_flag);

    // 2) fp16 conversion: A standalone; F fused with memory-bank update
    convert_a_kernel<<<(B_SZ * D_SZ / 4) / 256, 256>>>(inputs);
    convert_update_kernel<<<N_SZ, 256>>>(inputs, features, out_feats);

    // 3) FP16 tensor-core GEMM — dominant
    {
        dim3 grid(B_SZ / 128, (N_SZ + 127) / 128);   // (8, 235), m fastest
        mma_gemm_kernel<<<grid, 256, SMEM_DYN>>>(out);
    }
}